// round 1
// baseline (speedup 1.0000x reference)
#include <cuda_runtime.h>
#include <cstdint>

#define B_SZ    2
#define S_LEN   2048
#define D_MODEL 1024
#define N_HEADS 16
#define HD      64
#define M_TOT   (B_SZ * S_LEN)   // 4096

// ---------------- scratch (device globals; no allocation allowed) ----------
__device__ float g_q[B_SZ * N_HEADS * S_LEN * HD];    // [B,H,S,hd]
__device__ float g_k[B_SZ * N_HEADS * S_LEN * HD];
__device__ float g_v[B_SZ * N_HEADS * S_LEN * HD];
__device__ float g_ctx[B_SZ * S_LEN * D_MODEL];       // [B,S,D]

// ===========================================================================
// GEMM 1: qkv = X[4096,1024] @ W[1024,3072] + b, scattered into q/k/v
// with head split [B,H,S,hd].
// 128x128x16 tiles, 256 threads, 8x8 per-thread microtile, fp32.
// ===========================================================================
__global__ __launch_bounds__(256) void qkv_gemm_kernel(
    const float* __restrict__ X,
    const float* __restrict__ W,
    const float* __restrict__ bias)
{
    __shared__ float As[16 * 128];   // As[kk][m]
    __shared__ float Bs[16 * 128];   // Bs[kk][n]

    const int n0 = blockIdx.x * 128;
    const int m0 = blockIdx.y * 128;
    const int t  = threadIdx.x;
    const int tr = t >> 4;           // 0..15  (row group)
    const int tc = t & 15;           // 0..15  (col group)

    float acc[8][8];
#pragma unroll
    for (int i = 0; i < 8; ++i)
#pragma unroll
        for (int j = 0; j < 8; ++j) acc[i][j] = 0.f;

    for (int k0 = 0; k0 < 1024; k0 += 16) {
        // load A tile 128x16 (transposed into As[kk][m]) and B tile 16x128
#pragma unroll
        for (int it = 0; it < 2; ++it) {
            int idx = t + 256 * it;           // float4 index, 0..511
            int arow = idx >> 2;              // 0..127
            int acv  = (idx & 3) << 2;        // 0,4,8,12
            float4 a = *(const float4*)(X + (size_t)(m0 + arow) * 1024 + k0 + acv);
            As[(acv + 0) * 128 + arow] = a.x;
            As[(acv + 1) * 128 + arow] = a.y;
            As[(acv + 2) * 128 + arow] = a.z;
            As[(acv + 3) * 128 + arow] = a.w;

            int brow = idx >> 5;              // 0..15
            int bcv  = (idx & 31) << 2;       // 0..124
            float4 b = *(const float4*)(W + (size_t)(k0 + brow) * 3072 + n0 + bcv);
            *(float4*)(Bs + brow * 128 + bcv) = b;
        }
        __syncthreads();

#pragma unroll
        for (int kk = 0; kk < 16; ++kk) {
            float4 a0 = *(const float4*)(As + kk * 128 + tr * 8);
            float4 a1 = *(const float4*)(As + kk * 128 + tr * 8 + 4);
            float4 b0 = *(const float4*)(Bs + kk * 128 + tc * 8);
            float4 b1 = *(const float4*)(Bs + kk * 128 + tc * 8 + 4);
            float av[8] = {a0.x, a0.y, a0.z, a0.w, a1.x, a1.y, a1.z, a1.w};
            float bv[8] = {b0.x, b0.y, b0.z, b0.w, b1.x, b1.y, b1.z, b1.w};
#pragma unroll
            for (int i = 0; i < 8; ++i)
#pragma unroll
                for (int j = 0; j < 8; ++j)
                    acc[i][j] = fmaf(av[i], bv[j], acc[i][j]);
        }
        __syncthreads();
    }

    // epilogue: add bias, scatter to q/k/v with head split.
    // n block of 8 never crosses a 64 (head) or 1024 (q/k/v) boundary.
    const int nbase = n0 + tc * 8;
    const int part  = nbase >> 10;          // 0=q 1=k 2=v
    const int d     = nbase & 1023;
    const int h     = d >> 6;
    const int dd    = d & 63;
    float* dst = (part == 0) ? g_q : ((part == 1) ? g_k : g_v);

    float bvs[8];
#pragma unroll
    for (int j = 0; j < 8; ++j) bvs[j] = bias[nbase + j];

#pragma unroll
    for (int i = 0; i < 8; ++i) {
        int m = m0 + tr * 8 + i;
        int b = m >> 11;            // /2048
        int s = m & 2047;
        float* p = dst + ((size_t)((b * N_HEADS + h) * S_LEN + s)) * HD + dd;
        float4 v0, v1;
        v0.x = acc[i][0] + bvs[0]; v0.y = acc[i][1] + bvs[1];
        v0.z = acc[i][2] + bvs[2]; v0.w = acc[i][3] + bvs[3];
        v1.x = acc[i][4] + bvs[4]; v1.y = acc[i][5] + bvs[5];
        v1.z = acc[i][6] + bvs[6]; v1.w = acc[i][7] + bvs[7];
        *(float4*)(p)     = v0;
        *(float4*)(p + 4) = v1;
    }
}

// ===========================================================================
// Flash attention (causal), fp32. One block per (bh, q_tile of 64).
// k-tile = 64. smem: Qt[d][q], Kt[d][k] (reused for Pt[k][q]), V[k][d].
// 128 threads; thread (r,c) owns scores rows r*8..r*8+7, cols c*4..c*4+3,
// and output rows r*8..+7, head-dims c*4..+3.
// ===========================================================================
__global__ __launch_bounds__(128) void attn_kernel()
{
    __shared__ float sQ[64 * 64];   // Qt[d][q] (pre-scaled by 1/8)
    __shared__ float sK[64 * 64];   // Kt[d][k] ; reused as Pt[k][q]
    __shared__ float sV[64 * 64];   // V[k][d]

    const int bh = blockIdx.y;                 // 0..31 (b*16+h)
    const int q0 = blockIdx.x * 64;
    const float* qb = g_q + (size_t)bh * S_LEN * HD;
    const float* kb = g_k + (size_t)bh * S_LEN * HD;
    const float* vb = g_v + (size_t)bh * S_LEN * HD;

    const int t = threadIdx.x;      // 0..127
    const int r = t >> 4;           // 0..7
    const int c = t & 15;           // 0..15

    // load Q tile transposed, pre-scaled by 1/sqrt(hd)=0.125
#pragma unroll
    for (int it = 0; it < 8; ++it) {
        int idx = t + 128 * it;          // float4 index 0..1023
        int row = idx >> 4;              // 0..63
        int dv  = (idx & 15) << 2;       // 0..60
        float4 qv = *(const float4*)(qb + (size_t)(q0 + row) * HD + dv);
        sQ[(dv + 0) * 64 + row] = qv.x * 0.125f;
        sQ[(dv + 1) * 64 + row] = qv.y * 0.125f;
        sQ[(dv + 2) * 64 + row] = qv.z * 0.125f;
        sQ[(dv + 3) * 64 + row] = qv.w * 0.125f;
    }

    float m_i[8], l_i[8], acc[8][4];
#pragma unroll
    for (int i = 0; i < 8; ++i) {
        m_i[i] = -1e30f; l_i[i] = 0.f;
#pragma unroll
        for (int j = 0; j < 4; ++j) acc[i][j] = 0.f;
    }

    const int ktiles = blockIdx.x + 1;   // causal: only tiles with k0 <= q0
    for (int kt = 0; kt < ktiles; ++kt) {
        const int k0 = kt * 64;
        __syncthreads();   // prior PV reads done (also covers Q-load on kt=0)

        // load K (transposed) and V tiles
#pragma unroll
        for (int it = 0; it < 8; ++it) {
            int idx = t + 128 * it;
            int row = idx >> 4;
            int dv  = (idx & 15) << 2;
            float4 kv = *(const float4*)(kb + (size_t)(k0 + row) * HD + dv);
            sK[(dv + 0) * 64 + row] = kv.x;
            sK[(dv + 1) * 64 + row] = kv.y;
            sK[(dv + 2) * 64 + row] = kv.z;
            sK[(dv + 3) * 64 + row] = kv.w;
            float4 vv = *(const float4*)(vb + (size_t)(k0 + row) * HD + dv);
            *(float4*)(sV + row * 64 + dv) = vv;
        }
        __syncthreads();

        // scores S[8][4] = Qt^T Kt  (already scaled)
        float sc[8][4];
#pragma unroll
        for (int i = 0; i < 8; ++i)
#pragma unroll
            for (int j = 0; j < 4; ++j) sc[i][j] = 0.f;

#pragma unroll 8
        for (int dk = 0; dk < 64; ++dk) {
            float4 a0 = *(const float4*)(sQ + dk * 64 + r * 8);
            float4 a1 = *(const float4*)(sQ + dk * 64 + r * 8 + 4);
            float4 bb = *(const float4*)(sK + dk * 64 + c * 4);
            float av[8] = {a0.x, a0.y, a0.z, a0.w, a1.x, a1.y, a1.z, a1.w};
            float bv[4] = {bb.x, bb.y, bb.z, bb.w};
#pragma unroll
            for (int i = 0; i < 8; ++i)
#pragma unroll
                for (int j = 0; j < 4; ++j)
                    sc[i][j] = fmaf(av[i], bv[j], sc[i][j]);
        }

        // causal mask
        const bool diag = (kt == blockIdx.x);
        if (diag) {
#pragma unroll
            for (int i = 0; i < 8; ++i) {
                int qg = q0 + r * 8 + i;
#pragma unroll
                for (int j = 0; j < 4; ++j) {
                    int kg = k0 + c * 4 + j;
                    if (kg > qg) sc[i][j] = -1e30f;
                }
            }
        }

        __syncthreads();   // all sK (K) reads finished before P overwrite

        // online softmax update; write P transposed into sK
#pragma unroll
        for (int i = 0; i < 8; ++i) {
            float mt = sc[i][0];
#pragma unroll
            for (int j = 1; j < 4; ++j) mt = fmaxf(mt, sc[i][j]);
#pragma unroll
            for (int off = 8; off > 0; off >>= 1)
                mt = fmaxf(mt, __shfl_xor_sync(0xffffffffu, mt, off));

            float mnew = fmaxf(m_i[i], mt);
            float scale = __expf(m_i[i] - mnew);
            float psum = 0.f;
#pragma unroll
            for (int j = 0; j < 4; ++j) {
                float p = __expf(sc[i][j] - mnew);
                psum += p;
                sK[(c * 4 + j) * 64 + (r * 8 + i)] = p;   // Pt[k][q]
            }
#pragma unroll
            for (int off = 8; off > 0; off >>= 1)
                psum += __shfl_xor_sync(0xffffffffu, psum, off);

            l_i[i] = l_i[i] * scale + psum;
            m_i[i] = mnew;
#pragma unroll
            for (int j = 0; j < 4; ++j) acc[i][j] *= scale;
        }
        __syncthreads();   // P visible

        // O += P @ V
#pragma unroll 8
        for (int kk = 0; kk < 64; ++kk) {
            float4 p0 = *(const float4*)(sK + kk * 64 + r * 8);
            float4 p1 = *(const float4*)(sK + kk * 64 + r * 8 + 4);
            float4 vv = *(const float4*)(sV + kk * 64 + c * 4);
            float pv[8] = {p0.x, p0.y, p0.z, p0.w, p1.x, p1.y, p1.z, p1.w};
            float vb4[4] = {vv.x, vv.y, vv.z, vv.w};
#pragma unroll
            for (int i = 0; i < 8; ++i)
#pragma unroll
                for (int j = 0; j < 4; ++j)
                    acc[i][j] = fmaf(pv[i], vb4[j], acc[i][j]);
        }
    }

    // epilogue: normalize and write ctx[b][s][h*64 + d]
    const int b = bh >> 4;
    const int h = bh & 15;
#pragma unroll
    for (int i = 0; i < 8; ++i) {
        int qg = q0 + r * 8 + i;
        float inv = 1.f / l_i[i];
        float4 o;
        o.x = acc[i][0] * inv; o.y = acc[i][1] * inv;
        o.z = acc[i][2] * inv; o.w = acc[i][3] * inv;
        *(float4*)(g_ctx + ((size_t)(b * S_LEN + qg)) * D_MODEL + h * HD + c * 4) = o;
    }
}

// ===========================================================================
// GEMM 2: out = ctx[4096,1024] @ Wp[1024,1024] + bp
// ===========================================================================
__global__ __launch_bounds__(256) void proj_gemm_kernel(
    const float* __restrict__ W,
    const float* __restrict__ bias,
    float* __restrict__ out)
{
    __shared__ float As[16 * 128];
    __shared__ float Bs[16 * 128];

    const int n0 = blockIdx.x * 128;
    const int m0 = blockIdx.y * 128;
    const int t  = threadIdx.x;
    const int tr = t >> 4;
    const int tc = t & 15;

    float acc[8][8];
#pragma unroll
    for (int i = 0; i < 8; ++i)
#pragma unroll
        for (int j = 0; j < 8; ++j) acc[i][j] = 0.f;

    for (int k0 = 0; k0 < 1024; k0 += 16) {
#pragma unroll
        for (int it = 0; it < 2; ++it) {
            int idx = t + 256 * it;
            int arow = idx >> 2;
            int acv  = (idx & 3) << 2;
            float4 a = *(const float4*)(g_ctx + (size_t)(m0 + arow) * 1024 + k0 + acv);
            As[(acv + 0) * 128 + arow] = a.x;
            As[(acv + 1) * 128 + arow] = a.y;
            As[(acv + 2) * 128 + arow] = a.z;
            As[(acv + 3) * 128 + arow] = a.w;

            int brow = idx >> 5;
            int bcv  = (idx & 31) << 2;
            float4 b = *(const float4*)(W + (size_t)(k0 + brow) * 1024 + n0 + bcv);
            *(float4*)(Bs + brow * 128 + bcv) = b;
        }
        __syncthreads();

#pragma unroll
        for (int kk = 0; kk < 16; ++kk) {
            float4 a0 = *(const float4*)(As + kk * 128 + tr * 8);
            float4 a1 = *(const float4*)(As + kk * 128 + tr * 8 + 4);
            float4 b0 = *(const float4*)(Bs + kk * 128 + tc * 8);
            float4 b1 = *(const float4*)(Bs + kk * 128 + tc * 8 + 4);
            float av[8] = {a0.x, a0.y, a0.z, a0.w, a1.x, a1.y, a1.z, a1.w};
            float bv[8] = {b0.x, b0.y, b0.z, b0.w, b1.x, b1.y, b1.z, b1.w};
#pragma unroll
            for (int i = 0; i < 8; ++i)
#pragma unroll
                for (int j = 0; j < 8; ++j)
                    acc[i][j] = fmaf(av[i], bv[j], acc[i][j]);
        }
        __syncthreads();
    }

    const int nbase = n0 + tc * 8;
    float bvs[8];
#pragma unroll
    for (int j = 0; j < 8; ++j) bvs[j] = bias[nbase + j];

#pragma unroll
    for (int i = 0; i < 8; ++i) {
        int m = m0 + tr * 8 + i;
        float* p = out + (size_t)m * 1024 + nbase;
        float4 v0, v1;
        v0.x = acc[i][0] + bvs[0]; v0.y = acc[i][1] + bvs[1];
        v0.z = acc[i][2] + bvs[2]; v0.w = acc[i][3] + bvs[3];
        v1.x = acc[i][4] + bvs[4]; v1.y = acc[i][5] + bvs[5];
        v1.z = acc[i][6] + bvs[6]; v1.w = acc[i][7] + bvs[7];
        *(float4*)(p)     = v0;
        *(float4*)(p + 4) = v1;
    }
}

// ===========================================================================
extern "C" void kernel_launch(void* const* d_in, const int* in_sizes, int n_in,
                              void* d_out, int out_size)
{
    const float* X  = (const float*)d_in[0];   // hidden_states [2,2048,1024]
    const float* Wa = (const float*)d_in[1];   // w_attn [1024,3072]
    const float* ba = (const float*)d_in[2];   // b_attn [3072]
    const float* Wp = (const float*)d_in[3];   // w_proj [1024,1024]
    const float* bp = (const float*)d_in[4];   // b_proj [1024]
    float* out = (float*)d_out;                // [2,2048,1024]

    qkv_gemm_kernel<<<dim3(24, 32), 256>>>(X, Wa, ba);
    attn_kernel<<<dim3(32, 32), 128>>>();
    proj_gemm_kernel<<<dim3(8, 32), 256>>>(Wp, bp, out);
}

// round 3
// speedup vs baseline: 1.8236x; 1.8236x over previous
#include <cuda_runtime.h>
#include <cuda_bf16.h>
#include <cstdint>

#define B_SZ    2
#define S_LEN   2048
#define D_MODEL 1024
#define N_HEADS 16
#define HD      64
#define M_TOT   (B_SZ * S_LEN)   // 4096

typedef __nv_bfloat16 bf16;
typedef __nv_bfloat162 bf162;

// ---------------- scratch (device globals; no allocation allowed) ----------
__device__ float g_ctx[B_SZ * S_LEN * D_MODEL];       // [B,S,D] fp32

// split bf16 operands
__device__ bf16 g_xhi[M_TOT * D_MODEL];               // hidden split
__device__ bf16 g_xlo[M_TOT * D_MODEL];
__device__ bf16 g_wahi[3 * D_MODEL * D_MODEL];        // w_attn^T split [3072][1024]
__device__ bf16 g_walo[3 * D_MODEL * D_MODEL];
__device__ bf16 g_wphi[D_MODEL * D_MODEL];            // w_proj^T split [1024][1024]
__device__ bf16 g_wplo[D_MODEL * D_MODEL];
__device__ bf16 g_chi[M_TOT * D_MODEL];               // ctx split
__device__ bf16 g_clo[M_TOT * D_MODEL];

// attention operands, split bf16, layout [B,H,S,hd] (hd contiguous)
__device__ bf16 g_qhi[B_SZ * N_HEADS * S_LEN * HD];   // pre-scaled by 0.125
__device__ bf16 g_qlo[B_SZ * N_HEADS * S_LEN * HD];
__device__ bf16 g_khi[B_SZ * N_HEADS * S_LEN * HD];
__device__ bf16 g_klo[B_SZ * N_HEADS * S_LEN * HD];
__device__ bf16 g_vhi[B_SZ * N_HEADS * S_LEN * HD];
__device__ bf16 g_vlo[B_SZ * N_HEADS * S_LEN * HD];

// ======================= helpers ===========================================
__device__ __forceinline__ uint32_t smem_u32(const void* p) {
    uint32_t a;
    asm("{ .reg .u64 t; cvta.to.shared.u64 t, %1; cvt.u32.u64 %0, t; }" : "=r"(a) : "l"(p));
    return a;
}
__device__ __forceinline__ void ldsm_x4(uint32_t (&r)[4], uint32_t addr) {
    asm volatile("ldmatrix.sync.aligned.m8n8.x4.shared.b16 {%0,%1,%2,%3}, [%4];"
        : "=r"(r[0]), "=r"(r[1]), "=r"(r[2]), "=r"(r[3]) : "r"(addr));
}
__device__ __forceinline__ void ldsm_x4_t(uint32_t (&r)[4], uint32_t addr) {
    asm volatile("ldmatrix.sync.aligned.m8n8.x4.trans.shared.b16 {%0,%1,%2,%3}, [%4];"
        : "=r"(r[0]), "=r"(r[1]), "=r"(r[2]), "=r"(r[3]) : "r"(addr));
}
__device__ __forceinline__ void mma16816(float (&c)[4], const uint32_t (&a)[4],
                                         uint32_t b0, uint32_t b1) {
    asm volatile("mma.sync.aligned.m16n8k16.row.col.f32.bf16.bf16.f32 "
        "{%0,%1,%2,%3}, {%4,%5,%6,%7}, {%8,%9}, {%0,%1,%2,%3};"
        : "+f"(c[0]), "+f"(c[1]), "+f"(c[2]), "+f"(c[3])
        : "r"(a[0]), "r"(a[1]), "r"(a[2]), "r"(a[3]), "r"(b0), "r"(b1));
}
__device__ __forceinline__ void bf16split(float v, bf16& h, bf16& l) {
    h = __float2bfloat16_rn(v);
    l = __float2bfloat16_rn(v - __bfloat162float(h));
}
__device__ __forceinline__ void split_pack(float p0, float p1, uint32_t& hi, uint32_t& lo) {
    bf16 h0, h1, l0, l1;
    bf16split(p0, h0, l0); bf16split(p1, h1, l1);
    bf162 H; H.x = h0; H.y = h1;
    bf162 L; L.x = l0; L.y = l1;
    hi = *(uint32_t*)&H; lo = *(uint32_t*)&L;
}

// ======================= conversion kernels ================================
__global__ void conv_x_split(const float* __restrict__ X) {
    int i = blockIdx.x * blockDim.x + threadIdx.x;     // float4 index
    float4 v = ((const float4*)X)[i];
    bf16 h0, h1, h2, h3, l0, l1, l2, l3;
    bf16split(v.x, h0, l0); bf16split(v.y, h1, l1);
    bf16split(v.z, h2, l2); bf16split(v.w, h3, l3);
    bf162 ha; ha.x = h0; ha.y = h1;  bf162 hb; hb.x = h2; hb.y = h3;
    bf162 la; la.x = l0; la.y = l1;  bf162 lb; lb.x = l2; lb.y = l3;
    ((bf162*)g_xhi)[i * 2]     = ha;
    ((bf162*)g_xhi)[i * 2 + 1] = hb;
    ((bf162*)g_xlo)[i * 2]     = la;
    ((bf162*)g_xlo)[i * 2 + 1] = lb;
}

__global__ void conv_ctx_split() {
    int i = blockIdx.x * blockDim.x + threadIdx.x;
    float4 v = ((const float4*)g_ctx)[i];
    bf16 h0, h1, h2, h3, l0, l1, l2, l3;
    bf16split(v.x, h0, l0); bf16split(v.y, h1, l1);
    bf16split(v.z, h2, l2); bf16split(v.w, h3, l3);
    bf162 ha; ha.x = h0; ha.y = h1;  bf162 hb; hb.x = h2; hb.y = h3;
    bf162 la; la.x = l0; la.y = l1;  bf162 lb; lb.x = l2; lb.y = l3;
    ((bf162*)g_chi)[i * 2]     = ha;
    ((bf162*)g_chi)[i * 2 + 1] = hb;
    ((bf162*)g_clo)[i * 2]     = la;
    ((bf162*)g_clo)[i * 2 + 1] = lb;
}

// transpose + split: W [K=1024][N] row-major  ->  Wt [N][1024]
template<int WHICH>  // 0: w_attn (N=3072), 1: w_proj (N=1024)
__global__ void conv_w_tsplit(const float* __restrict__ W, int N) {
    __shared__ float tile[32][33];
    int x = blockIdx.x * 32 + threadIdx.x;       // n
#pragma unroll
    for (int r = 0; r < 4; ++r) {
        int y = blockIdx.y * 32 + threadIdx.y + r * 8;   // k
        tile[threadIdx.y + r * 8][threadIdx.x] = W[(size_t)y * N + x];
    }
    __syncthreads();
    int k = blockIdx.y * 32 + threadIdx.x;
    bf16* Hi = (WHICH == 0) ? g_wahi : g_wphi;
    bf16* Lo = (WHICH == 0) ? g_walo : g_wplo;
#pragma unroll
    for (int r = 0; r < 4; ++r) {
        int n = blockIdx.x * 32 + threadIdx.y + r * 8;
        float v = tile[threadIdx.x][threadIdx.y + r * 8];
        bf16 h, l; bf16split(v, h, l);
        Hi[(size_t)n * 1024 + k] = h;
        Lo[(size_t)n * 1024 + k] = l;
    }
}

// ======================= HMMA split-bf16 GEMM ==============================
// C[M,N] = A[M,1024]@B[N,1024]^T via K'=3072 (hi*hi + lo*hi + hi*lo).
// 256 threads (8 warps, 2x4 warp grid, warp tile 64x32), tile 128x128,
// K-chunk 32 bf16 (64B rows), double-buffered smem, XOR swizzle.
template<int MODE>   // 0 = qkv (N=3072, scatter split q/k/v), 1 = proj
__global__ void __launch_bounds__(256) hmma_gemm(
    const float* __restrict__ bias, float* __restrict__ out)
{
    __shared__ __align__(16) uint8_t smA[2][8192];
    __shared__ __align__(16) uint8_t smB[2][8192];

    const int t  = threadIdx.x;
    const int w  = t >> 5, l = t & 31;
    const int m0 = blockIdx.y * 128;
    const int n0 = blockIdx.x * 128;
    const int wm = (w >> 2) * 64;
    const int wn = (w & 3) * 32;

    const bf16* Ahi = (MODE == 0) ? g_xhi : g_chi;
    const bf16* Alo = (MODE == 0) ? g_xlo : g_clo;
    const bf16* Bhi = (MODE == 0) ? g_wahi : g_wphi;
    const bf16* Blo = (MODE == 0) ? g_walo : g_wplo;

    float acc[4][4][4];
#pragma unroll
    for (int i = 0; i < 4; ++i)
#pragma unroll
        for (int j = 0; j < 4; ++j)
#pragma unroll
            for (int v = 0; v < 4; ++v) acc[i][j][v] = 0.f;

    const bool isB = (t >= 128);
    const int lrow = t & 127;

    auto loadChunk = [&](int kc, int stage) {
        const int seg  = kc >> 5;
        const int koff = (kc & 31) * 32;
        const bf16* src = isB ? ((seg == 2) ? Blo : Bhi) + (size_t)(n0 + lrow) * 1024 + koff
                              : ((seg == 1) ? Alo : Ahi) + (size_t)(m0 + lrow) * 1024 + koff;
        uint8_t* dst = isB ? smB[stage] : smA[stage];
#pragma unroll
        for (int c = 0; c < 4; ++c) {
            uint4 v = *(const uint4*)(src + c * 8);
            uint32_t sw = lrow * 64 + ((c ^ ((lrow >> 1) & 3)) << 4);
            *(uint4*)(dst + sw) = v;
        }
    };

    loadChunk(0, 0);

    for (int kc = 0; kc < 96; ++kc) {
        __syncthreads();
        if (kc + 1 < 96) loadChunk(kc + 1, (kc + 1) & 1);

        const uint32_t bA = smem_u32(smA[kc & 1]);
        const uint32_t bB = smem_u32(smB[kc & 1]);
#pragma unroll
        for (int kt = 0; kt < 2; ++kt) {
            uint32_t a[4][4];
#pragma unroll
            for (int mi = 0; mi < 4; ++mi) {
                int r = wm + 16 * mi + (l & 15);
                int c = 2 * kt + (l >> 4);
                ldsm_x4(a[mi], bA + r * 64 + ((c ^ ((r >> 1) & 3)) << 4));
            }
            uint32_t b[2][4];
#pragma unroll
            for (int nfp = 0; nfp < 2; ++nfp) {
                int r = wn + 16 * nfp + (l & 7) + ((l >> 4) & 1) * 8;
                int c = 2 * kt + ((l >> 3) & 1);
                ldsm_x4(b[nfp], bB + r * 64 + ((c ^ ((r >> 1) & 3)) << 4));
            }
#pragma unroll
            for (int mi = 0; mi < 4; ++mi)
#pragma unroll
                for (int nfp = 0; nfp < 2; ++nfp) {
                    mma16816(acc[mi][2 * nfp],     a[mi], b[nfp][0], b[nfp][1]);
                    mma16816(acc[mi][2 * nfp + 1], a[mi], b[nfp][2], b[nfp][3]);
                }
        }
    }

    // ---------------- epilogue ----------------
#pragma unroll
    for (int mi = 0; mi < 4; ++mi) {
#pragma unroll
        for (int ni = 0; ni < 4; ++ni) {
            int gr = m0 + wm + 16 * mi + (l >> 2);
            int gc = n0 + wn + 8 * ni + 2 * (l & 3);
            float b0 = bias[gc], b1 = bias[gc + 1];
#pragma unroll
            for (int h2 = 0; h2 < 2; ++h2) {
                int row = gr + 8 * h2;
                float v0 = acc[mi][ni][2 * h2]     + b0;
                float v1 = acc[mi][ni][2 * h2 + 1] + b1;
                if (MODE == 1) {
                    float2 o; o.x = v0; o.y = v1;
                    *(float2*)(out + (size_t)row * 1024 + gc) = o;
                } else {
                    int part = n0 >> 10;               // uniform per block
                    int rem  = gc & 1023;
                    int hh   = rem >> 6, dd = rem & 63;
                    int bb   = row >> 11, s = row & 2047;
                    size_t idx = (((size_t)(bb * 16 + hh) * 2048) + s) * 64 + dd;
                    if (part == 0) { v0 *= 0.125f; v1 *= 0.125f; }
                    bf16 h0, h1, l0, l1;
                    bf16split(v0, h0, l0); bf16split(v1, h1, l1);
                    bf162 H; H.x = h0; H.y = h1;
                    bf162 L; L.x = l0; L.y = l1;
                    bf16* dHi = (part == 0) ? g_qhi : ((part == 1) ? g_khi : g_vhi);
                    bf16* dLo = (part == 0) ? g_qlo : ((part == 1) ? g_klo : g_vlo);
                    *(bf162*)(dHi + idx) = H;
                    *(bf162*)(dLo + idx) = L;
                }
            }
        }
    }
}

// ======================= HMMA flash attention ==============================
// Block: (q-tile 64, bh). 128 threads = 4 warps; warp w owns q rows 16w..16w+15.
// S = Q K^T (3-pass split), online softmax in accum frags, P repacked in-reg
// as A-frags (split), O += P V (3-pass, V via ldmatrix.trans).
__global__ void __launch_bounds__(128) attn_hmma()
{
    __shared__ __align__(16) uint8_t sKh[8192], sKl[8192], sVh[8192], sVl[8192];

    const int t  = threadIdx.x;
    const int w  = t >> 5, l = t & 31;
    const int qt = blockIdx.x;
    const int bh = blockIdx.y;
    const int q0 = qt * 64;

    const bf16* qh = g_qhi + (size_t)bh * S_LEN * HD;
    const bf16* ql = g_qlo + (size_t)bh * S_LEN * HD;
    const bf16* kh = g_khi + (size_t)bh * S_LEN * HD;
    const bf16* kl = g_klo + (size_t)bh * S_LEN * HD;
    const bf16* vh = g_vhi + (size_t)bh * S_LEN * HD;
    const bf16* vl = g_vlo + (size_t)bh * S_LEN * HD;

    // Q A-fragments (hi & lo) straight from gmem; live in regs for the kernel
    uint32_t aQh[4][4], aQl[4][4];
    const int gr = q0 + w * 16 + (l >> 2);
#pragma unroll
    for (int t16 = 0; t16 < 4; ++t16) {
#pragma unroll
        for (int rg = 0; rg < 4; ++rg) {
            int row = gr + (rg & 1) * 8;
            int col = 16 * t16 + 2 * (l & 3) + (rg >> 1) * 8;
            aQh[t16][rg] = *(const uint32_t*)(qh + (size_t)row * HD + col);
            aQl[t16][rg] = *(const uint32_t*)(ql + (size_t)row * HD + col);
        }
    }

    float m_i[2] = {-1e30f, -1e30f};
    float l_i[2] = {0.f, 0.f};
    float o[8][4];
#pragma unroll
    for (int nf = 0; nf < 8; ++nf)
#pragma unroll
        for (int v = 0; v < 4; ++v) o[nf][v] = 0.f;

    const uint32_t bKh = smem_u32(sKh), bKl = smem_u32(sKl);
    const uint32_t bVh = smem_u32(sVh), bVl = smem_u32(sVl);

    for (int kt = 0; kt <= qt; ++kt) {
        const int k0 = kt * 64;
        __syncthreads();
        // load K,V hi/lo tiles (64 rows x 128B each), swizzled
        {
            const int r = t >> 1;
            const bf16* s0 = kh + (size_t)(k0 + r) * HD;
            const bf16* s1 = kl + (size_t)(k0 + r) * HD;
            const bf16* s2 = vh + (size_t)(k0 + r) * HD;
            const bf16* s3 = vl + (size_t)(k0 + r) * HD;
#pragma unroll
            for (int i = 0; i < 4; ++i) {
                int seg = (t & 1) * 4 + i;
                uint32_t sw = r * 128 + ((seg ^ (r & 7)) << 4);
                *(uint4*)(sKh + sw) = *(const uint4*)(s0 + seg * 8);
                *(uint4*)(sKl + sw) = *(const uint4*)(s1 + seg * 8);
                *(uint4*)(sVh + sw) = *(const uint4*)(s2 + seg * 8);
                *(uint4*)(sVl + sw) = *(const uint4*)(s3 + seg * 8);
            }
        }
        __syncthreads();

        // ---- S = Q K^T (3-pass) ----
        float sc[8][4];
#pragma unroll
        for (int nf = 0; nf < 8; ++nf)
#pragma unroll
            for (int v = 0; v < 4; ++v) sc[nf][v] = 0.f;

#pragma unroll
        for (int t16 = 0; t16 < 4; ++t16) {
#pragma unroll
            for (int nfp = 0; nfp < 4; ++nfp) {
                int r = 16 * nfp + (l & 7) + ((l >> 4) & 1) * 8;
                int c = 2 * t16 + ((l >> 3) & 1);
                uint32_t off = r * 128 + ((c ^ (r & 7)) << 4);
                uint32_t kh4[4], kl4[4];
                ldsm_x4(kh4, bKh + off);
                ldsm_x4(kl4, bKl + off);
                mma16816(sc[2 * nfp],     aQh[t16], kh4[0], kh4[1]);
                mma16816(sc[2 * nfp],     aQh[t16], kl4[0], kl4[1]);
                mma16816(sc[2 * nfp],     aQl[t16], kh4[0], kh4[1]);
                mma16816(sc[2 * nfp + 1], aQh[t16], kh4[2], kh4[3]);
                mma16816(sc[2 * nfp + 1], aQh[t16], kl4[2], kl4[3]);
                mma16816(sc[2 * nfp + 1], aQl[t16], kh4[2], kh4[3]);
            }
        }

        // causal mask on diagonal tile
        if (kt == qt) {
#pragma unroll
            for (int nf = 0; nf < 8; ++nf)
#pragma unroll
                for (int v = 0; v < 4; ++v) {
                    int kg = k0 + 8 * nf + 2 * (l & 3) + (v & 1);
                    int qg = gr + 8 * (v >> 1);
                    if (kg > qg) sc[nf][v] = -1e30f;
                }
        }

        // ---- online softmax ----
#pragma unroll
        for (int h = 0; h < 2; ++h) {
            float mt = -1e30f;
#pragma unroll
            for (int nf = 0; nf < 8; ++nf) {
                mt = fmaxf(mt, sc[nf][2 * h]);
                mt = fmaxf(mt, sc[nf][2 * h + 1]);
            }
            mt = fmaxf(mt, __shfl_xor_sync(0xffffffffu, mt, 1));
            mt = fmaxf(mt, __shfl_xor_sync(0xffffffffu, mt, 2));
            float mnew = fmaxf(m_i[h], mt);
            float corr = __expf(m_i[h] - mnew);
            float psum = 0.f;
#pragma unroll
            for (int nf = 0; nf < 8; ++nf) {
                float p0 = __expf(sc[nf][2 * h]     - mnew);
                float p1 = __expf(sc[nf][2 * h + 1] - mnew);
                sc[nf][2 * h] = p0; sc[nf][2 * h + 1] = p1;
                psum += p0 + p1;
            }
            psum += __shfl_xor_sync(0xffffffffu, psum, 1);
            psum += __shfl_xor_sync(0xffffffffu, psum, 2);
            l_i[h] = l_i[h] * corr + psum;
            m_i[h] = mnew;
#pragma unroll
            for (int nf = 0; nf < 8; ++nf) {
                o[nf][2 * h]     *= corr;
                o[nf][2 * h + 1] *= corr;
            }
        }

        // ---- repack P as split A-frags ----
        uint32_t aPh[4][4], aPl[4][4];
#pragma unroll
        for (int t16 = 0; t16 < 4; ++t16) {
            split_pack(sc[2 * t16][0],     sc[2 * t16][1],     aPh[t16][0], aPl[t16][0]);
            split_pack(sc[2 * t16][2],     sc[2 * t16][3],     aPh[t16][1], aPl[t16][1]);
            split_pack(sc[2 * t16 + 1][0], sc[2 * t16 + 1][1], aPh[t16][2], aPl[t16][2]);
            split_pack(sc[2 * t16 + 1][2], sc[2 * t16 + 1][3], aPh[t16][3], aPl[t16][3]);
        }

        // ---- O += P V (3-pass, V transposed via ldmatrix.trans) ----
#pragma unroll
        for (int t16 = 0; t16 < 4; ++t16) {
#pragma unroll
            for (int nfp = 0; nfp < 4; ++nfp) {
                int r = 16 * t16 + (l & 7) + ((l >> 3) & 1) * 8;
                int c = 2 * nfp + ((l >> 4) & 1);
                uint32_t off = r * 128 + ((c ^ (r & 7)) << 4);
                uint32_t vh4[4], vl4[4];
                ldsm_x4_t(vh4, bVh + off);
                ldsm_x4_t(vl4, bVl + off);
                mma16816(o[2 * nfp],     aPh[t16], vh4[0], vh4[1]);
                mma16816(o[2 * nfp],     aPh[t16], vl4[0], vl4[1]);
                mma16816(o[2 * nfp],     aPl[t16], vh4[0], vh4[1]);
                mma16816(o[2 * nfp + 1], aPh[t16], vh4[2], vh4[3]);
                mma16816(o[2 * nfp + 1], aPh[t16], vl4[2], vl4[3]);
                mma16816(o[2 * nfp + 1], aPl[t16], vh4[2], vh4[3]);
            }
        }
    }

    // ---- epilogue: normalize, write ctx fp32 ----
    const int bb = bh >> 4, hh = bh & 15;
#pragma unroll
    for (int h = 0; h < 2; ++h) {
        float inv = 1.f / l_i[h];
        int row = gr + 8 * h;
#pragma unroll
        for (int nf = 0; nf < 8; ++nf) {
            int d = 8 * nf + 2 * (l & 3);
            float2 ov;
            ov.x = o[nf][2 * h]     * inv;
            ov.y = o[nf][2 * h + 1] * inv;
            *(float2*)(g_ctx + ((size_t)(bb * S_LEN + row)) * D_MODEL + hh * HD + d) = ov;
        }
    }
}

// ===========================================================================
extern "C" void kernel_launch(void* const* d_in, const int* in_sizes, int n_in,
                              void* d_out, int out_size)
{
    const float* X  = (const float*)d_in[0];   // hidden_states [2,2048,1024]
    const float* Wa = (const float*)d_in[1];   // w_attn [1024,3072]
    const float* ba = (const float*)d_in[2];   // b_attn [3072]
    const float* Wp = (const float*)d_in[3];   // w_proj [1024,1024]
    const float* bp = (const float*)d_in[4];   // b_proj [1024]
    float* out = (float*)d_out;                // [2,2048,1024]

    conv_x_split<<<(M_TOT * D_MODEL / 4) / 256, 256>>>(X);
    conv_w_tsplit<0><<<dim3(96, 32), dim3(32, 8)>>>(Wa, 3072);
    conv_w_tsplit<1><<<dim3(32, 32), dim3(32, 8)>>>(Wp, 1024);

    hmma_gemm<0><<<dim3(24, 32), 256>>>(ba, out);
    attn_hmma<<<dim3(32, 32), 128>>>();
    conv_ctx_split<<<(M_TOT * D_MODEL / 4) / 256, 256>>>();
    hmma_gemm<1><<<dim3(8, 32), 256>>>(bp, out);
}

// round 4
// speedup vs baseline: 3.2264x; 1.7692x over previous
#include <cuda_runtime.h>
#include <cuda_bf16.h>
#include <cstdint>

#define B_SZ    2
#define S_LEN   2048
#define D_MODEL 1024
#define N_HEADS 16
#define HD      64
#define M_TOT   (B_SZ * S_LEN)   // 4096

typedef __nv_bfloat16 bf16;
typedef __nv_bfloat162 bf162;

// ---------------- scratch (device globals; no allocation allowed) ----------
__device__ bf16 g_xhi[M_TOT * D_MODEL];               // hidden split
__device__ bf16 g_xlo[M_TOT * D_MODEL];
__device__ bf16 g_wahi[3 * D_MODEL * D_MODEL];        // w_attn^T split [3072][1024]
__device__ bf16 g_walo[3 * D_MODEL * D_MODEL];
__device__ bf16 g_wphi[D_MODEL * D_MODEL];            // w_proj^T split [1024][1024]
__device__ bf16 g_wplo[D_MODEL * D_MODEL];
__device__ bf16 g_chi[M_TOT * D_MODEL];               // ctx split (written by attn)
__device__ bf16 g_clo[M_TOT * D_MODEL];

// attention operands, split bf16, layout [B,H,S,hd]
__device__ bf16 g_qhi[B_SZ * N_HEADS * S_LEN * HD];   // pre-scaled by 0.125
__device__ bf16 g_qlo[B_SZ * N_HEADS * S_LEN * HD];
__device__ bf16 g_khi[B_SZ * N_HEADS * S_LEN * HD];
__device__ bf16 g_klo[B_SZ * N_HEADS * S_LEN * HD];
__device__ bf16 g_vhi[B_SZ * N_HEADS * S_LEN * HD];
__device__ bf16 g_vlo[B_SZ * N_HEADS * S_LEN * HD];

// ======================= helpers ===========================================
__device__ __forceinline__ uint32_t smem_u32(const void* p) {
    uint32_t a;
    asm("{ .reg .u64 t; cvta.to.shared.u64 t, %1; cvt.u32.u64 %0, t; }" : "=r"(a) : "l"(p));
    return a;
}
__device__ __forceinline__ void ldsm_x4(uint32_t (&r)[4], uint32_t addr) {
    asm volatile("ldmatrix.sync.aligned.m8n8.x4.shared.b16 {%0,%1,%2,%3}, [%4];"
        : "=r"(r[0]), "=r"(r[1]), "=r"(r[2]), "=r"(r[3]) : "r"(addr));
}
__device__ __forceinline__ void ldsm_x4_t(uint32_t (&r)[4], uint32_t addr) {
    asm volatile("ldmatrix.sync.aligned.m8n8.x4.trans.shared.b16 {%0,%1,%2,%3}, [%4];"
        : "=r"(r[0]), "=r"(r[1]), "=r"(r[2]), "=r"(r[3]) : "r"(addr));
}
__device__ __forceinline__ void mma16816(float (&c)[4], const uint32_t (&a)[4],
                                         uint32_t b0, uint32_t b1) {
    asm volatile("mma.sync.aligned.m16n8k16.row.col.f32.bf16.bf16.f32 "
        "{%0,%1,%2,%3}, {%4,%5,%6,%7}, {%8,%9}, {%0,%1,%2,%3};"
        : "+f"(c[0]), "+f"(c[1]), "+f"(c[2]), "+f"(c[3])
        : "r"(a[0]), "r"(a[1]), "r"(a[2]), "r"(a[3]), "r"(b0), "r"(b1));
}
__device__ __forceinline__ void cp16(uint32_t dst, const void* src) {
    asm volatile("cp.async.cg.shared.global [%0], [%1], 16;" :: "r"(dst), "l"(src));
}
#define CP_COMMIT() asm volatile("cp.async.commit_group;" ::: "memory")
#define CP_WAIT0()  asm volatile("cp.async.wait_group 0;" ::: "memory")
#define CP_WAIT1()  asm volatile("cp.async.wait_group 1;" ::: "memory")

__device__ __forceinline__ void bf16split(float v, bf16& h, bf16& l) {
    h = __float2bfloat16_rn(v);
    l = __float2bfloat16_rn(v - __bfloat162float(h));
}
__device__ __forceinline__ void split_pack(float p0, float p1, uint32_t& hi, uint32_t& lo) {
    bf16 h0, h1, l0, l1;
    bf16split(p0, h0, l0); bf16split(p1, h1, l1);
    bf162 H; H.x = h0; H.y = h1;
    bf162 L; L.x = l0; L.y = l1;
    hi = *(uint32_t*)&H; lo = *(uint32_t*)&L;
}

// ======================= conversion kernels ================================
__global__ void conv_x_split(const float* __restrict__ X) {
    int i = blockIdx.x * blockDim.x + threadIdx.x;     // float4 index
    float4 v = ((const float4*)X)[i];
    bf16 h0, h1, h2, h3, l0, l1, l2, l3;
    bf16split(v.x, h0, l0); bf16split(v.y, h1, l1);
    bf16split(v.z, h2, l2); bf16split(v.w, h3, l3);
    bf162 ha; ha.x = h0; ha.y = h1;  bf162 hb; hb.x = h2; hb.y = h3;
    bf162 la; la.x = l0; la.y = l1;  bf162 lb; lb.x = l2; lb.y = l3;
    ((bf162*)g_xhi)[i * 2]     = ha;
    ((bf162*)g_xhi)[i * 2 + 1] = hb;
    ((bf162*)g_xlo)[i * 2]     = la;
    ((bf162*)g_xlo)[i * 2 + 1] = lb;
}

// transpose + split: W [K=1024][N] row-major  ->  Wt [N][1024]
template<int WHICH>  // 0: w_attn (N=3072), 1: w_proj (N=1024)
__global__ void conv_w_tsplit(const float* __restrict__ W, int N) {
    __shared__ float tile[32][33];
    int x = blockIdx.x * 32 + threadIdx.x;       // n
#pragma unroll
    for (int r = 0; r < 4; ++r) {
        int y = blockIdx.y * 32 + threadIdx.y + r * 8;   // k
        tile[threadIdx.y + r * 8][threadIdx.x] = W[(size_t)y * N + x];
    }
    __syncthreads();
    int k = blockIdx.y * 32 + threadIdx.x;
    bf16* Hi = (WHICH == 0) ? g_wahi : g_wphi;
    bf16* Lo = (WHICH == 0) ? g_walo : g_wplo;
#pragma unroll
    for (int r = 0; r < 4; ++r) {
        int n = blockIdx.x * 32 + threadIdx.y + r * 8;
        float v = tile[threadIdx.x][threadIdx.y + r * 8];
        bf16 h, l; bf16split(v, h, l);
        Hi[(size_t)n * 1024 + k] = h;
        Lo[(size_t)n * 1024 + k] = l;
    }
}

// ======================= HMMA split-bf16 GEMM ==============================
// C[M,N] = A[M,1024]@B[N,1024]^T via K'=3072 (hi*hi + lo*hi + hi*lo).
// Block 128x256, 8 warps (2x4), warp tile 64x64, BK=64 (128B SW128 rows),
// 3-stage cp.async pipeline.
#define GEMM_STAGE_BYTES 49152               // A 16K + B 32K
#define GEMM_SMEM_BYTES  (3 * GEMM_STAGE_BYTES)
#define NKC 48

template<int MODE>   // 0 = qkv (scatter split q/k/v), 1 = proj (dense fp32 out)
__global__ void __launch_bounds__(256, 1) hmma_gemm(
    const float* __restrict__ bias, float* __restrict__ out)
{
    extern __shared__ __align__(16) uint8_t sm[];
    const int t  = threadIdx.x;
    const int w  = t >> 5, l = t & 31;
    const int m0 = blockIdx.y * 128;
    const int n0 = blockIdx.x * 256;
    const int wm = (w & 1) * 64;
    const int wn = (w >> 1) * 64;

    const bf16* Ahi = (MODE == 0) ? g_xhi : g_chi;
    const bf16* Alo = (MODE == 0) ? g_xlo : g_clo;
    const bf16* Bhi = (MODE == 0) ? g_wahi : g_wphi;
    const bf16* Blo = (MODE == 0) ? g_walo : g_wplo;

    float acc[4][8][4];
#pragma unroll
    for (int i = 0; i < 4; ++i)
#pragma unroll
        for (int j = 0; j < 8; ++j)
#pragma unroll
            for (int v = 0; v < 4; ++v) acc[i][j][v] = 0.f;

    auto stage_load = [&](int kc, int st) {
        const int kg   = kc * 64;
        const int seg  = kg >> 10;
        const int koff = kg & 1023;
        const bf16* Asrc = (seg == 1) ? Alo : Ahi;
        const bf16* Bsrc = (seg == 2) ? Blo : Bhi;
        uint32_t sA = smem_u32(sm) + st * GEMM_STAGE_BYTES;
        uint32_t sB = sA + 16384;
#pragma unroll
        for (int i = 0; i < 4; ++i) {
            int idx = t + 256 * i;
            int row = idx >> 3, sg = idx & 7;
            cp16(sA + row * 128 + ((sg ^ (row & 7)) << 4),
                 Asrc + (size_t)(m0 + row) * 1024 + koff + sg * 8);
        }
#pragma unroll
        for (int i = 0; i < 8; ++i) {
            int idx = t + 256 * i;
            int row = idx >> 3, sg = idx & 7;
            cp16(sB + row * 128 + ((sg ^ (row & 7)) << 4),
                 Bsrc + (size_t)(n0 + row) * 1024 + koff + sg * 8);
        }
        CP_COMMIT();
    };

    stage_load(0, 0);
    stage_load(1, 1);

    for (int kc = 0; kc < NKC; ++kc) {
        if (kc == NKC - 1) { CP_WAIT0(); } else { CP_WAIT1(); }
        __syncthreads();
        if (kc + 2 < NKC) stage_load(kc + 2, (kc + 2) % 3);

        const uint32_t bA = smem_u32(sm) + (kc % 3) * GEMM_STAGE_BYTES;
        const uint32_t bB = bA + 16384;
#pragma unroll
        for (int kt = 0; kt < 4; ++kt) {
            uint32_t a[4][4];
#pragma unroll
            for (int mi = 0; mi < 4; ++mi) {
                int r = wm + 16 * mi + (l & 15);
                int c = 2 * kt + (l >> 4);
                ldsm_x4(a[mi], bA + r * 128 + ((c ^ (r & 7)) << 4));
            }
#pragma unroll
            for (int ni2 = 0; ni2 < 4; ++ni2) {
                uint32_t b[4];
                int r = wn + 16 * ni2 + (l & 7) + ((l >> 4) & 1) * 8;
                int c = 2 * kt + ((l >> 3) & 1);
                ldsm_x4(b, bB + r * 128 + ((c ^ (r & 7)) << 4));
#pragma unroll
                for (int mi = 0; mi < 4; ++mi) {
                    mma16816(acc[mi][2 * ni2],     a[mi], b[0], b[1]);
                    mma16816(acc[mi][2 * ni2 + 1], a[mi], b[2], b[3]);
                }
            }
        }
    }

    // ---------------- epilogue ----------------
    const int part = n0 >> 10;   // uniform per block (n-tile 256 within 1024 part)
#pragma unroll
    for (int mi = 0; mi < 4; ++mi) {
#pragma unroll
        for (int ni = 0; ni < 8; ++ni) {
            int gr = m0 + wm + 16 * mi + (l >> 2);
            int gc = n0 + wn + 8 * ni + 2 * (l & 3);
            float b0 = bias[gc], b1 = bias[gc + 1];
#pragma unroll
            for (int h2 = 0; h2 < 2; ++h2) {
                int row = gr + 8 * h2;
                float v0 = acc[mi][ni][2 * h2]     + b0;
                float v1 = acc[mi][ni][2 * h2 + 1] + b1;
                if (MODE == 1) {
                    float2 o; o.x = v0; o.y = v1;
                    *(float2*)(out + (size_t)row * 1024 + gc) = o;
                } else {
                    int rem = gc & 1023;
                    int hh  = rem >> 6, dd = rem & 63;
                    int bb  = row >> 11, s = row & 2047;
                    size_t idx = (((size_t)(bb * 16 + hh) * 2048) + s) * 64 + dd;
                    if (part == 0) { v0 *= 0.125f; v1 *= 0.125f; }
                    uint32_t H, L;
                    split_pack(v0, v1, H, L);
                    bf16* dHi = (part == 0) ? g_qhi : ((part == 1) ? g_khi : g_vhi);
                    bf16* dLo = (part == 0) ? g_qlo : ((part == 1) ? g_klo : g_vlo);
                    *(uint32_t*)(dHi + idx) = H;
                    *(uint32_t*)(dLo + idx) = L;
                }
            }
        }
    }
}

// ======================= HMMA flash attention ==============================
// Block: (q-tile 128, bh). 256 threads = 8 warps; warp w owns q rows 16w..16w+15.
// k-tile 64. S = Q K^T (3-pass split), online softmax, P repacked in-reg,
// O += P V (3-pass, V via ldmatrix.trans). Writes split bf16 ctx directly.
__global__ void __launch_bounds__(256) attn_hmma()
{
    __shared__ __align__(16) uint8_t sKh[8192], sKl[8192], sVh[8192], sVl[8192];

    const int t  = threadIdx.x;
    const int w  = t >> 5, l = t & 31;
    const int qt = blockIdx.x;
    const int bh = blockIdx.y;
    const int q0 = qt * 128;

    const bf16* qh = g_qhi + (size_t)bh * S_LEN * HD;
    const bf16* ql = g_qlo + (size_t)bh * S_LEN * HD;
    const bf16* kh = g_khi + (size_t)bh * S_LEN * HD;
    const bf16* kl = g_klo + (size_t)bh * S_LEN * HD;
    const bf16* vh = g_vhi + (size_t)bh * S_LEN * HD;
    const bf16* vl = g_vlo + (size_t)bh * S_LEN * HD;

    // Q A-fragments (hi & lo) straight from gmem; live in regs
    uint32_t aQh[4][4], aQl[4][4];
    const int gr = q0 + w * 16 + (l >> 2);
#pragma unroll
    for (int t16 = 0; t16 < 4; ++t16) {
#pragma unroll
        for (int rg = 0; rg < 4; ++rg) {
            int row = gr + (rg & 1) * 8;
            int col = 16 * t16 + 2 * (l & 3) + (rg >> 1) * 8;
            aQh[t16][rg] = *(const uint32_t*)(qh + (size_t)row * HD + col);
            aQl[t16][rg] = *(const uint32_t*)(ql + (size_t)row * HD + col);
        }
    }

    float m_i[2] = {-1e30f, -1e30f};
    float l_i[2] = {0.f, 0.f};
    float o[8][4];
#pragma unroll
    for (int nf = 0; nf < 8; ++nf)
#pragma unroll
        for (int v = 0; v < 4; ++v) o[nf][v] = 0.f;

    const uint32_t bKh = smem_u32(sKh), bKl = smem_u32(sKl);
    const uint32_t bVh = smem_u32(sVh), bVl = smem_u32(sVl);

    const int ktiles = 2 * qt + 2;
    for (int kt = 0; kt < ktiles; ++kt) {
        const int k0 = kt * 64;
        __syncthreads();   // prior tile's smem reads done
        // load K,V hi/lo tiles via cp.async (each: 64 rows x 128B)
#pragma unroll
        for (int i = 0; i < 2; ++i) {
            int idx = t + 256 * i;
            int row = idx >> 3, sg = idx & 7;
            uint32_t sw = row * 128 + ((sg ^ (row & 7)) << 4);
            size_t goff = (size_t)(k0 + row) * HD + sg * 8;
            cp16(bKh + sw, kh + goff);
            cp16(bKl + sw, kl + goff);
            cp16(bVh + sw, vh + goff);
            cp16(bVl + sw, vl + goff);
        }
        CP_COMMIT();
        CP_WAIT0();
        __syncthreads();

        // warps whose rows are all below this k-tile skip compute entirely
        if (k0 > q0 + w * 16 + 15) continue;

        // ---- S = Q K^T (3-pass) ----
        float sc[8][4];
#pragma unroll
        for (int nf = 0; nf < 8; ++nf)
#pragma unroll
            for (int v = 0; v < 4; ++v) sc[nf][v] = 0.f;

#pragma unroll
        for (int t16 = 0; t16 < 4; ++t16) {
#pragma unroll
            for (int nfp = 0; nfp < 4; ++nfp) {
                int r = 16 * nfp + (l & 7) + ((l >> 4) & 1) * 8;
                int c = 2 * t16 + ((l >> 3) & 1);
                uint32_t off = r * 128 + ((c ^ (r & 7)) << 4);
                uint32_t kh4[4], kl4[4];
                ldsm_x4(kh4, bKh + off);
                ldsm_x4(kl4, bKl + off);
                mma16816(sc[2 * nfp],     aQh[t16], kh4[0], kh4[1]);
                mma16816(sc[2 * nfp],     aQh[t16], kl4[0], kl4[1]);
                mma16816(sc[2 * nfp],     aQl[t16], kh4[0], kh4[1]);
                mma16816(sc[2 * nfp + 1], aQh[t16], kh4[2], kh4[3]);
                mma16816(sc[2 * nfp + 1], aQh[t16], kl4[2], kl4[3]);
                mma16816(sc[2 * nfp + 1], aQl[t16], kh4[2], kh4[3]);
            }
        }

        // causal mask (only tiles overlapping the diagonal of this warp)
        if (k0 + 63 > q0 + w * 16) {
#pragma unroll
            for (int nf = 0; nf < 8; ++nf)
#pragma unroll
                for (int v = 0; v < 4; ++v) {
                    int kg = k0 + 8 * nf + 2 * (l & 3) + (v & 1);
                    int qg = gr + 8 * (v >> 1);
                    if (kg > qg) sc[nf][v] = -1e30f;
                }
        }

        // ---- online softmax ----
#pragma unroll
        for (int h = 0; h < 2; ++h) {
            float mt = -1e30f;
#pragma unroll
            for (int nf = 0; nf < 8; ++nf) {
                mt = fmaxf(mt, sc[nf][2 * h]);
                mt = fmaxf(mt, sc[nf][2 * h + 1]);
            }
            mt = fmaxf(mt, __shfl_xor_sync(0xffffffffu, mt, 1));
            mt = fmaxf(mt, __shfl_xor_sync(0xffffffffu, mt, 2));
            float mnew = fmaxf(m_i[h], mt);
            float corr = __expf(m_i[h] - mnew);
            float psum = 0.f;
#pragma unroll
            for (int nf = 0; nf < 8; ++nf) {
                float p0 = __expf(sc[nf][2 * h]     - mnew);
                float p1 = __expf(sc[nf][2 * h + 1] - mnew);
                sc[nf][2 * h] = p0; sc[nf][2 * h + 1] = p1;
                psum += p0 + p1;
            }
            psum += __shfl_xor_sync(0xffffffffu, psum, 1);
            psum += __shfl_xor_sync(0xffffffffu, psum, 2);
            l_i[h] = l_i[h] * corr + psum;
            m_i[h] = mnew;
#pragma unroll
            for (int nf = 0; nf < 8; ++nf) {
                o[nf][2 * h]     *= corr;
                o[nf][2 * h + 1] *= corr;
            }
        }

        // ---- repack P as split A-frags ----
        uint32_t aPh[4][4], aPl[4][4];
#pragma unroll
        for (int t16 = 0; t16 < 4; ++t16) {
            split_pack(sc[2 * t16][0],     sc[2 * t16][1],     aPh[t16][0], aPl[t16][0]);
            split_pack(sc[2 * t16][2],     sc[2 * t16][3],     aPh[t16][1], aPl[t16][1]);
            split_pack(sc[2 * t16 + 1][0], sc[2 * t16 + 1][1], aPh[t16][2], aPl[t16][2]);
            split_pack(sc[2 * t16 + 1][2], sc[2 * t16 + 1][3], aPh[t16][3], aPl[t16][3]);
        }

        // ---- O += P V (3-pass, V transposed via ldmatrix.trans) ----
#pragma unroll
        for (int t16 = 0; t16 < 4; ++t16) {
#pragma unroll
            for (int nfp = 0; nfp < 4; ++nfp) {
                int r = 16 * t16 + (l & 7) + ((l >> 3) & 1) * 8;
                int c = 2 * nfp + ((l >> 4) & 1);
                uint32_t off = r * 128 + ((c ^ (r & 7)) << 4);
                uint32_t vh4[4], vl4[4];
                ldsm_x4_t(vh4, bVh + off);
                ldsm_x4_t(vl4, bVl + off);
                mma16816(o[2 * nfp],     aPh[t16], vh4[0], vh4[1]);
                mma16816(o[2 * nfp],     aPh[t16], vl4[0], vl4[1]);
                mma16816(o[2 * nfp],     aPl[t16], vh4[0], vh4[1]);
                mma16816(o[2 * nfp + 1], aPh[t16], vh4[2], vh4[3]);
                mma16816(o[2 * nfp + 1], aPh[t16], vl4[2], vl4[3]);
                mma16816(o[2 * nfp + 1], aPl[t16], vh4[2], vh4[3]);
            }
        }
    }

    // ---- epilogue: normalize, split, write ctx as bf16 hi/lo ----
    const int bb = bh >> 4, hh = bh & 15;
#pragma unroll
    for (int h = 0; h < 2; ++h) {
        float inv = 1.f / l_i[h];
        int row = gr + 8 * h;
#pragma unroll
        for (int nf = 0; nf < 8; ++nf) {
            int d = 8 * nf + 2 * (l & 3);
            size_t idx = ((size_t)(bb * S_LEN + row)) * D_MODEL + hh * HD + d;
            uint32_t H, L;
            split_pack(o[nf][2 * h] * inv, o[nf][2 * h + 1] * inv, H, L);
            *(uint32_t*)(g_chi + idx) = H;
            *(uint32_t*)(g_clo + idx) = L;
        }
    }
}

// ===========================================================================
extern "C" void kernel_launch(void* const* d_in, const int* in_sizes, int n_in,
                              void* d_out, int out_size)
{
    const float* X  = (const float*)d_in[0];   // hidden_states [2,2048,1024]
    const float* Wa = (const float*)d_in[1];   // w_attn [1024,3072]
    const float* ba = (const float*)d_in[2];   // b_attn [3072]
    const float* Wp = (const float*)d_in[3];   // w_proj [1024,1024]
    const float* bp = (const float*)d_in[4];   // b_proj [1024]
    float* out = (float*)d_out;                // [2,2048,1024]

    cudaFuncSetAttribute(hmma_gemm<0>,
                         cudaFuncAttributeMaxDynamicSharedMemorySize, GEMM_SMEM_BYTES);
    cudaFuncSetAttribute(hmma_gemm<1>,
                         cudaFuncAttributeMaxDynamicSharedMemorySize, GEMM_SMEM_BYTES);

    conv_x_split<<<(M_TOT * D_MODEL / 4) / 256, 256>>>(X);
    conv_w_tsplit<0><<<dim3(96, 32), dim3(32, 8)>>>(Wa, 3072);
    conv_w_tsplit<1><<<dim3(32, 32), dim3(32, 8)>>>(Wp, 1024);

    hmma_gemm<0><<<dim3(12, 32), 256, GEMM_SMEM_BYTES>>>(ba, out);
    attn_hmma<<<dim3(16, 32), 256>>>();
    hmma_gemm<1><<<dim3(4, 32), 256, GEMM_SMEM_BYTES>>>(bp, out);
}

// round 5
// speedup vs baseline: 3.5921x; 1.1134x over previous
#include <cuda_runtime.h>
#include <cuda_bf16.h>
#include <cstdint>

#define B_SZ    2
#define S_LEN   2048
#define D_MODEL 1024
#define N_HEADS 16
#define HD      64
#define M_TOT   (B_SZ * S_LEN)   // 4096

typedef __nv_bfloat16 bf16;
typedef __nv_bfloat162 bf162;

// ---------------- scratch (device globals; no allocation allowed) ----------
__device__ bf16 g_xhi[M_TOT * D_MODEL];               // hidden split
__device__ bf16 g_xlo[M_TOT * D_MODEL];
__device__ bf16 g_wahi[3 * D_MODEL * D_MODEL];        // w_attn^T split [3072][1024]
__device__ bf16 g_walo[3 * D_MODEL * D_MODEL];
__device__ bf16 g_wphi[D_MODEL * D_MODEL];            // w_proj^T split [1024][1024]
__device__ bf16 g_wplo[D_MODEL * D_MODEL];
__device__ bf16 g_chi[M_TOT * D_MODEL];               // ctx split (written by attn)
__device__ bf16 g_clo[M_TOT * D_MODEL];

// attention operands, split bf16, layout [B,H,S,hd]
__device__ bf16 g_qhi[B_SZ * N_HEADS * S_LEN * HD];   // pre-scaled by 0.125
__device__ bf16 g_qlo[B_SZ * N_HEADS * S_LEN * HD];
__device__ bf16 g_khi[B_SZ * N_HEADS * S_LEN * HD];
__device__ bf16 g_klo[B_SZ * N_HEADS * S_LEN * HD];
__device__ bf16 g_vhi[B_SZ * N_HEADS * S_LEN * HD];
__device__ bf16 g_vlo[B_SZ * N_HEADS * S_LEN * HD];

// ======================= helpers ===========================================
__device__ __forceinline__ uint32_t smem_u32(const void* p) {
    uint32_t a;
    asm("{ .reg .u64 t; cvta.to.shared.u64 t, %1; cvt.u32.u64 %0, t; }" : "=r"(a) : "l"(p));
    return a;
}
__device__ __forceinline__ void ldsm_x4(uint32_t (&r)[4], uint32_t addr) {
    asm volatile("ldmatrix.sync.aligned.m8n8.x4.shared.b16 {%0,%1,%2,%3}, [%4];"
        : "=r"(r[0]), "=r"(r[1]), "=r"(r[2]), "=r"(r[3]) : "r"(addr));
}
__device__ __forceinline__ void ldsm_x4_t(uint32_t (&r)[4], uint32_t addr) {
    asm volatile("ldmatrix.sync.aligned.m8n8.x4.trans.shared.b16 {%0,%1,%2,%3}, [%4];"
        : "=r"(r[0]), "=r"(r[1]), "=r"(r[2]), "=r"(r[3]) : "r"(addr));
}
__device__ __forceinline__ void mma16816(float (&c)[4], const uint32_t (&a)[4],
                                         uint32_t b0, uint32_t b1) {
    asm volatile("mma.sync.aligned.m16n8k16.row.col.f32.bf16.bf16.f32 "
        "{%0,%1,%2,%3}, {%4,%5,%6,%7}, {%8,%9}, {%0,%1,%2,%3};"
        : "+f"(c[0]), "+f"(c[1]), "+f"(c[2]), "+f"(c[3])
        : "r"(a[0]), "r"(a[1]), "r"(a[2]), "r"(a[3]), "r"(b0), "r"(b1));
}
__device__ __forceinline__ void cp16(uint32_t dst, const void* src) {
    asm volatile("cp.async.cg.shared.global [%0], [%1], 16;" :: "r"(dst), "l"(src));
}
#define CP_COMMIT() asm volatile("cp.async.commit_group;" ::: "memory")
#define CP_WAIT0()  asm volatile("cp.async.wait_group 0;" ::: "memory")
#define CP_WAIT1()  asm volatile("cp.async.wait_group 1;" ::: "memory")

// fast split: cvt.rn.bf16x2 + residual
__device__ __forceinline__ void split_pack(float p0, float p1, uint32_t& hi, uint32_t& lo) {
    uint32_t H;
    asm("cvt.rn.bf16x2.f32 %0, %1, %2;" : "=r"(H) : "f"(p1), "f"(p0));
    float h0 = __uint_as_float(H << 16);
    float h1 = __uint_as_float(H & 0xffff0000u);
    float l0 = p0 - h0, l1 = p1 - h1;
    uint32_t L;
    asm("cvt.rn.bf16x2.f32 %0, %1, %2;" : "=r"(L) : "f"(l1), "f"(l0));
    hi = H; lo = L;
}
__device__ __forceinline__ void bf16split(float v, bf16& h, bf16& l) {
    h = __float2bfloat16_rn(v);
    l = __float2bfloat16_rn(v - __bfloat162float(h));
}

// ======================= conversion kernels ================================
__global__ void conv_x_split(const float* __restrict__ X) {
    int i = blockIdx.x * blockDim.x + threadIdx.x;     // float4 index
    float4 v = ((const float4*)X)[i];
    uint32_t h01, l01, h23, l23;
    split_pack(v.x, v.y, h01, l01);
    split_pack(v.z, v.w, h23, l23);
    ((uint32_t*)g_xhi)[i * 2]     = h01;
    ((uint32_t*)g_xhi)[i * 2 + 1] = h23;
    ((uint32_t*)g_xlo)[i * 2]     = l01;
    ((uint32_t*)g_xlo)[i * 2 + 1] = l23;
}

// transpose + split: W [K=1024][N] row-major  ->  Wt [N][1024]
template<int WHICH>  // 0: w_attn (N=3072), 1: w_proj (N=1024)
__global__ void conv_w_tsplit(const float* __restrict__ W, int N) {
    __shared__ float tile[32][33];
    int x = blockIdx.x * 32 + threadIdx.x;       // n
#pragma unroll
    for (int r = 0; r < 4; ++r) {
        int y = blockIdx.y * 32 + threadIdx.y + r * 8;   // k
        tile[threadIdx.y + r * 8][threadIdx.x] = W[(size_t)y * N + x];
    }
    __syncthreads();
    int k = blockIdx.y * 32 + threadIdx.x;
    bf16* Hi = (WHICH == 0) ? g_wahi : g_wphi;
    bf16* Lo = (WHICH == 0) ? g_walo : g_wplo;
#pragma unroll
    for (int r = 0; r < 4; ++r) {
        int n = blockIdx.x * 32 + threadIdx.y + r * 8;
        float v = tile[threadIdx.x][threadIdx.y + r * 8];
        bf16 h, l; bf16split(v, h, l);
        Hi[(size_t)n * 1024 + k] = h;
        Lo[(size_t)n * 1024 + k] = l;
    }
}

// ======================= HMMA split-bf16 GEMM ==============================
// C[M,N] = A[M,1024]@B[N,1024]^T via K'=3072 (hi*hi + lo*hi + hi*lo).
// Block 128x128, 4 warps (2x2), warp tile 64x64, BK=64 (128B SW128 rows),
// 3-stage cp.async pipeline, 2 CTAs/SM for latency overlap.
#define GEMM_STAGE_BYTES 32768               // A 16K + B 16K
#define GEMM_SMEM_BYTES  (3 * GEMM_STAGE_BYTES)
#define NKC 48

template<int MODE>   // 0 = qkv (scatter split q/k/v), 1 = proj (dense fp32 out)
__global__ void __launch_bounds__(128, 2) hmma_gemm(
    const float* __restrict__ bias, float* __restrict__ out)
{
    extern __shared__ __align__(16) uint8_t sm[];
    const int t  = threadIdx.x;
    const int w  = t >> 5, l = t & 31;
    const int m0 = blockIdx.y * 128;
    const int n0 = blockIdx.x * 128;
    const int wm = (w & 1) * 64;
    const int wn = (w >> 1) * 64;

    const bf16* Ahi = (MODE == 0) ? g_xhi : g_chi;
    const bf16* Alo = (MODE == 0) ? g_xlo : g_clo;
    const bf16* Bhi = (MODE == 0) ? g_wahi : g_wphi;
    const bf16* Blo = (MODE == 0) ? g_walo : g_wplo;

    float acc[4][8][4];
#pragma unroll
    for (int i = 0; i < 4; ++i)
#pragma unroll
        for (int j = 0; j < 8; ++j)
#pragma unroll
            for (int v = 0; v < 4; ++v) acc[i][j][v] = 0.f;

    auto stage_load = [&](int kc, int st) {
        const int kg   = kc * 64;
        const int seg  = kg >> 10;
        const int koff = kg & 1023;
        const bf16* Asrc = (seg == 1) ? Alo : Ahi;
        const bf16* Bsrc = (seg == 2) ? Blo : Bhi;
        uint32_t sA = smem_u32(sm) + st * GEMM_STAGE_BYTES;
        uint32_t sB = sA + 16384;
#pragma unroll
        for (int i = 0; i < 8; ++i) {
            int idx = t + 128 * i;
            int row = idx >> 3, sg = idx & 7;
            cp16(sA + row * 128 + ((sg ^ (row & 7)) << 4),
                 Asrc + (size_t)(m0 + row) * 1024 + koff + sg * 8);
        }
#pragma unroll
        for (int i = 0; i < 8; ++i) {
            int idx = t + 128 * i;
            int row = idx >> 3, sg = idx & 7;
            cp16(sB + row * 128 + ((sg ^ (row & 7)) << 4),
                 Bsrc + (size_t)(n0 + row) * 1024 + koff + sg * 8);
        }
        CP_COMMIT();
    };

    stage_load(0, 0);
    stage_load(1, 1);

    for (int kc = 0; kc < NKC; ++kc) {
        if (kc == NKC - 1) { CP_WAIT0(); } else { CP_WAIT1(); }
        __syncthreads();
        if (kc + 2 < NKC) stage_load(kc + 2, (kc + 2) % 3);

        const uint32_t bA = smem_u32(sm) + (kc % 3) * GEMM_STAGE_BYTES;
        const uint32_t bB = bA + 16384;
#pragma unroll
        for (int kt = 0; kt < 4; ++kt) {
            uint32_t a[4][4];
#pragma unroll
            for (int mi = 0; mi < 4; ++mi) {
                int r = wm + 16 * mi + (l & 15);
                int c = 2 * kt + (l >> 4);
                ldsm_x4(a[mi], bA + r * 128 + ((c ^ (r & 7)) << 4));
            }
#pragma unroll
            for (int ni2 = 0; ni2 < 4; ++ni2) {
                uint32_t b[4];
                int r = wn + 16 * ni2 + (l & 7) + ((l >> 4) & 1) * 8;
                int c = 2 * kt + ((l >> 3) & 1);
                ldsm_x4(b, bB + r * 128 + ((c ^ (r & 7)) << 4));
#pragma unroll
                for (int mi = 0; mi < 4; ++mi) {
                    mma16816(acc[mi][2 * ni2],     a[mi], b[0], b[1]);
                    mma16816(acc[mi][2 * ni2 + 1], a[mi], b[2], b[3]);
                }
            }
        }
    }

    // ---------------- epilogue ----------------
    const int part = n0 >> 10;   // uniform per block (128 | 1024)
#pragma unroll
    for (int mi = 0; mi < 4; ++mi) {
#pragma unroll
        for (int ni = 0; ni < 8; ++ni) {
            int gr = m0 + wm + 16 * mi + (l >> 2);
            int gc = n0 + wn + 8 * ni + 2 * (l & 3);
            float b0 = bias[gc], b1 = bias[gc + 1];
#pragma unroll
            for (int h2 = 0; h2 < 2; ++h2) {
                int row = gr + 8 * h2;
                float v0 = acc[mi][ni][2 * h2]     + b0;
                float v1 = acc[mi][ni][2 * h2 + 1] + b1;
                if (MODE == 1) {
                    float2 o; o.x = v0; o.y = v1;
                    *(float2*)(out + (size_t)row * 1024 + gc) = o;
                } else {
                    int rem = gc & 1023;
                    int hh  = rem >> 6, dd = rem & 63;
                    int bb  = row >> 11, s = row & 2047;
                    size_t idx = (((size_t)(bb * 16 + hh) * 2048) + s) * 64 + dd;
                    if (part == 0) { v0 *= 0.125f; v1 *= 0.125f; }
                    uint32_t H, L;
                    split_pack(v0, v1, H, L);
                    bf16* dHi = (part == 0) ? g_qhi : ((part == 1) ? g_khi : g_vhi);
                    bf16* dLo = (part == 0) ? g_qlo : ((part == 1) ? g_klo : g_vlo);
                    *(uint32_t*)(dHi + idx) = H;
                    *(uint32_t*)(dLo + idx) = L;
                }
            }
        }
    }
}

// ======================= HMMA flash attention ==============================
// Block: (q-tile 128, bh). 256 threads = 8 warps; warp w owns q rows 16w..16w+15.
// k-tile 64, double-buffered cp.async K/V. Split bf16 ctx written directly.
__global__ void __launch_bounds__(256) attn_hmma()
{
    // 2 stages x (Kh,Kl,Vh,Vl) x 8KB
    __shared__ __align__(16) uint8_t sKV[2][4][8192];

    const int t  = threadIdx.x;
    const int w  = t >> 5, l = t & 31;
    const int qt = blockIdx.x;
    const int bh = blockIdx.y;
    const int q0 = qt * 128;

    const bf16* qh = g_qhi + (size_t)bh * S_LEN * HD;
    const bf16* ql = g_qlo + (size_t)bh * S_LEN * HD;
    const bf16* kh = g_khi + (size_t)bh * S_LEN * HD;
    const bf16* kl = g_klo + (size_t)bh * S_LEN * HD;
    const bf16* vh = g_vhi + (size_t)bh * S_LEN * HD;
    const bf16* vl = g_vlo + (size_t)bh * S_LEN * HD;

    // Q A-fragments (hi & lo) straight from gmem; live in regs
    uint32_t aQh[4][4], aQl[4][4];
    const int gr = q0 + w * 16 + (l >> 2);
#pragma unroll
    for (int t16 = 0; t16 < 4; ++t16) {
#pragma unroll
        for (int rg = 0; rg < 4; ++rg) {
            int row = gr + (rg & 1) * 8;
            int col = 16 * t16 + 2 * (l & 3) + (rg >> 1) * 8;
            aQh[t16][rg] = *(const uint32_t*)(qh + (size_t)row * HD + col);
            aQl[t16][rg] = *(const uint32_t*)(ql + (size_t)row * HD + col);
        }
    }

    float m_i[2] = {-1e30f, -1e30f};
    float l_i[2] = {0.f, 0.f};
    float o[8][4];
#pragma unroll
    for (int nf = 0; nf < 8; ++nf)
#pragma unroll
        for (int v = 0; v < 4; ++v) o[nf][v] = 0.f;

    auto load_tile = [&](int kt) {
        const int st = kt & 1;
        const int k0 = kt * 64;
#pragma unroll
        for (int i = 0; i < 2; ++i) {
            int idx = t + 256 * i;
            int row = idx >> 3, sg = idx & 7;
            uint32_t sw = row * 128 + ((sg ^ (row & 7)) << 4);
            size_t goff = (size_t)(k0 + row) * HD + sg * 8;
            cp16(smem_u32(sKV[st][0]) + sw, kh + goff);
            cp16(smem_u32(sKV[st][1]) + sw, kl + goff);
            cp16(smem_u32(sKV[st][2]) + sw, vh + goff);
            cp16(smem_u32(sKV[st][3]) + sw, vl + goff);
        }
        CP_COMMIT();
    };

    const int ktiles = 2 * qt + 2;
    load_tile(0);

    for (int kt = 0; kt < ktiles; ++kt) {
        const int k0 = kt * 64;
        if (kt + 1 < ktiles) { load_tile(kt + 1); CP_WAIT1(); }
        else                 { CP_WAIT0(); }
        __syncthreads();

        const int st = kt & 1;
        const uint32_t bKh = smem_u32(sKV[st][0]);
        const uint32_t bKl = smem_u32(sKV[st][1]);
        const uint32_t bVh = smem_u32(sKV[st][2]);
        const uint32_t bVl = smem_u32(sKV[st][3]);

        // warps whose rows are all below this k-tile skip compute
        if (k0 <= q0 + w * 16 + 15) {
            // ---- S = Q K^T (3-pass) ----
            float sc[8][4];
#pragma unroll
            for (int nf = 0; nf < 8; ++nf)
#pragma unroll
                for (int v = 0; v < 4; ++v) sc[nf][v] = 0.f;

#pragma unroll
            for (int t16 = 0; t16 < 4; ++t16) {
#pragma unroll
                for (int nfp = 0; nfp < 4; ++nfp) {
                    int r = 16 * nfp + (l & 7) + ((l >> 4) & 1) * 8;
                    int c = 2 * t16 + ((l >> 3) & 1);
                    uint32_t off = r * 128 + ((c ^ (r & 7)) << 4);
                    uint32_t kh4[4], kl4[4];
                    ldsm_x4(kh4, bKh + off);
                    ldsm_x4(kl4, bKl + off);
                    mma16816(sc[2 * nfp],     aQh[t16], kh4[0], kh4[1]);
                    mma16816(sc[2 * nfp],     aQh[t16], kl4[0], kl4[1]);
                    mma16816(sc[2 * nfp],     aQl[t16], kh4[0], kh4[1]);
                    mma16816(sc[2 * nfp + 1], aQh[t16], kh4[2], kh4[3]);
                    mma16816(sc[2 * nfp + 1], aQh[t16], kl4[2], kl4[3]);
                    mma16816(sc[2 * nfp + 1], aQl[t16], kh4[2], kh4[3]);
                }
            }

            // causal mask (only tiles overlapping this warp's diagonal)
            if (k0 + 63 > q0 + w * 16) {
#pragma unroll
                for (int nf = 0; nf < 8; ++nf)
#pragma unroll
                    for (int v = 0; v < 4; ++v) {
                        int kg = k0 + 8 * nf + 2 * (l & 3) + (v & 1);
                        int qg = gr + 8 * (v >> 1);
                        if (kg > qg) sc[nf][v] = -1e30f;
                    }
            }

            // ---- online softmax ----
#pragma unroll
            for (int h = 0; h < 2; ++h) {
                float mt = -1e30f;
#pragma unroll
                for (int nf = 0; nf < 8; ++nf) {
                    mt = fmaxf(mt, sc[nf][2 * h]);
                    mt = fmaxf(mt, sc[nf][2 * h + 1]);
                }
                mt = fmaxf(mt, __shfl_xor_sync(0xffffffffu, mt, 1));
                mt = fmaxf(mt, __shfl_xor_sync(0xffffffffu, mt, 2));
                float mnew = fmaxf(m_i[h], mt);
                float corr = __expf(m_i[h] - mnew);
                float psum = 0.f;
#pragma unroll
                for (int nf = 0; nf < 8; ++nf) {
                    float p0 = __expf(sc[nf][2 * h]     - mnew);
                    float p1 = __expf(sc[nf][2 * h + 1] - mnew);
                    sc[nf][2 * h] = p0; sc[nf][2 * h + 1] = p1;
                    psum += p0 + p1;
                }
                psum += __shfl_xor_sync(0xffffffffu, psum, 1);
                psum += __shfl_xor_sync(0xffffffffu, psum, 2);
                l_i[h] = l_i[h] * corr + psum;
                m_i[h] = mnew;
#pragma unroll
                for (int nf = 0; nf < 8; ++nf) {
                    o[nf][2 * h]     *= corr;
                    o[nf][2 * h + 1] *= corr;
                }
            }

            // ---- repack P as split A-frags ----
            uint32_t aPh[4][4], aPl[4][4];
#pragma unroll
            for (int t16 = 0; t16 < 4; ++t16) {
                split_pack(sc[2 * t16][0],     sc[2 * t16][1],     aPh[t16][0], aPl[t16][0]);
                split_pack(sc[2 * t16][2],     sc[2 * t16][3],     aPh[t16][1], aPl[t16][1]);
                split_pack(sc[2 * t16 + 1][0], sc[2 * t16 + 1][1], aPh[t16][2], aPl[t16][2]);
                split_pack(sc[2 * t16 + 1][2], sc[2 * t16 + 1][3], aPh[t16][3], aPl[t16][3]);
            }

            // ---- O += P V (3-pass, V transposed via ldmatrix.trans) ----
#pragma unroll
            for (int t16 = 0; t16 < 4; ++t16) {
#pragma unroll
                for (int nfp = 0; nfp < 4; ++nfp) {
                    int r = 16 * t16 + (l & 7) + ((l >> 3) & 1) * 8;
                    int c = 2 * nfp + ((l >> 4) & 1);
                    uint32_t off = r * 128 + ((c ^ (r & 7)) << 4);
                    uint32_t vh4[4], vl4[4];
                    ldsm_x4_t(vh4, bVh + off);
                    ldsm_x4_t(vl4, bVl + off);
                    mma16816(o[2 * nfp],     aPh[t16], vh4[0], vh4[1]);
                    mma16816(o[2 * nfp],     aPh[t16], vl4[0], vl4[1]);
                    mma16816(o[2 * nfp],     aPl[t16], vh4[0], vh4[1]);
                    mma16816(o[2 * nfp + 1], aPh[t16], vh4[2], vh4[3]);
                    mma16816(o[2 * nfp + 1], aPh[t16], vl4[2], vl4[3]);
                    mma16816(o[2 * nfp + 1], aPl[t16], vh4[2], vh4[3]);
                }
            }
        }
        __syncthreads();   // stage reads done before it is overwritten
    }

    // ---- epilogue: normalize, split, write ctx as bf16 hi/lo ----
    const int bb = bh >> 4, hh = bh & 15;
#pragma unroll
    for (int h = 0; h < 2; ++h) {
        float inv = 1.f / l_i[h];
        int row = gr + 8 * h;
#pragma unroll
        for (int nf = 0; nf < 8; ++nf) {
            int d = 8 * nf + 2 * (l & 3);
            size_t idx = ((size_t)(bb * S_LEN + row)) * D_MODEL + hh * HD + d;
            uint32_t H, L;
            split_pack(o[nf][2 * h] * inv, o[nf][2 * h + 1] * inv, H, L);
            *(uint32_t*)(g_chi + idx) = H;
            *(uint32_t*)(g_clo + idx) = L;
        }
    }
}

// ===========================================================================
extern "C" void kernel_launch(void* const* d_in, const int* in_sizes, int n_in,
                              void* d_out, int out_size)
{
    const float* X  = (const float*)d_in[0];   // hidden_states [2,2048,1024]
    const float* Wa = (const float*)d_in[1];   // w_attn [1024,3072]
    const float* ba = (const float*)d_in[2];   // b_attn [3072]
    const float* Wp = (const float*)d_in[3];   // w_proj [1024,1024]
    const float* bp = (const float*)d_in[4];   // b_proj [1024]
    float* out = (float*)d_out;                // [2,2048,1024]

    cudaFuncSetAttribute(hmma_gemm<0>,
                         cudaFuncAttributeMaxDynamicSharedMemorySize, GEMM_SMEM_BYTES);
    cudaFuncSetAttribute(hmma_gemm<1>,
                         cudaFuncAttributeMaxDynamicSharedMemorySize, GEMM_SMEM_BYTES);

    conv_x_split<<<(M_TOT * D_MODEL / 4) / 256, 256>>>(X);
    conv_w_tsplit<0><<<dim3(96, 32), dim3(32, 8)>>>(Wa, 3072);
    conv_w_tsplit<1><<<dim3(32, 32), dim3(32, 8)>>>(Wp, 1024);

    hmma_gemm<0><<<dim3(24, 32), 128, GEMM_SMEM_BYTES>>>(ba, out);
    attn_hmma<<<dim3(16, 32), 256>>>();
    hmma_gemm<1><<<dim3(8, 32), 128, GEMM_SMEM_BYTES>>>(bp, out);
}